// round 1
// baseline (speedup 1.0000x reference)
#include <cuda_runtime.h>

#define F0 339
#define F1 5825
#define F2 64
#define NROWS 6228      // F0 + F1 + F2
#define RK 128
#define CH 256

// Scratch (allowed: __device__ globals, no allocation)
__device__ float g_P[NROWS * CH];
__device__ float g_Q[NROWS * CH];
__device__ int g_idx64;

// ---------------------------------------------------------------------------
// Index-dtype detection: for little-endian int64 data with values < 6000, every
// odd 32-bit word is 0. For int32 data, odd words are mode-1 indices in
// [0,5825) — probability all 128 are zero is ~(1/5825)^128 ~ 0.
// ---------------------------------------------------------------------------
__global__ void detect_idx_kernel(const unsigned int* __restrict__ w) {
    if (threadIdx.x == 0) {
        int allz = 1;
        #pragma unroll 1
        for (int i = 1; i < 256; i += 2) allz &= (w[i] == 0u);
        g_idx64 = allz;
    }
}

// Block -> (table, global row base, valid rows) mapping. 32 rows per block.
// ceil(339/32)=11, ceil(5825/32)=183, ceil(64/32)=2  -> 196 blocks total.
__device__ __forceinline__ void block_map(int b, int& table, int& gbase, int& lbase, int& rows) {
    if (b < 11)       { table = 0; int f = b * 32;         lbase = f; gbase = f;            rows = min(32, F0 - f); }
    else if (b < 194) { table = 1; int f = (b - 11) * 32;  lbase = f; gbase = F0 + f;       rows = min(32, F1 - f); }
    else              { table = 2; int f = (b - 194) * 32; lbase = f; gbase = F0 + F1 + f;  rows = min(32, F2 - f); }
}

// ---------------------------------------------------------------------------
// Kernel A1:  P[f, c] = relu( sum_r E[f, r] * w1[c, r] + b1[c] )
// One block = 32 rows of the concatenated table. w1 staged in smem with
// padded stride 129 (conflict-free column reads).
// ---------------------------------------------------------------------------
#define SMEM_A1 ((256 * 129 + 32 * 128) * 4)
__global__ __launch_bounds__(256) void kA1(
    const float* __restrict__ emb0, const float* __restrict__ emb1,
    const float* __restrict__ emb2,
    const float* __restrict__ w1, const float* __restrict__ b1)
{
    extern __shared__ float sm[];
    float* w1s = sm;              // [256][129]
    float* Es  = sm + 256 * 129;  // [32][128]

    int table, gbase, lbase, rows;
    block_map(blockIdx.x, table, gbase, lbase, rows);
    const float* E = (table == 0) ? emb0 : ((table == 1) ? emb1 : emb2);

    int tid = threadIdx.x;
    for (int idx = tid; idx < 256 * 128; idx += 256) {
        int c = idx >> 7, r = idx & 127;
        w1s[c * 129 + r] = w1[idx];
    }
    for (int idx = tid; idx < 32 * 128; idx += 256) {
        int rr = idx >> 7, r = idx & 127;
        Es[idx] = (rr < rows) ? E[(long long)(lbase + rr) * RK + r] : 0.f;
    }
    __syncthreads();

    int tc = tid & 31, tr = tid >> 5;
    float acc[8][4];
    #pragma unroll
    for (int i = 0; i < 8; i++)
        #pragma unroll
        for (int q = 0; q < 4; q++) acc[i][q] = 0.f;

    #pragma unroll 4
    for (int r = 0; r < 128; r++) {
        float w[8], e[4];
        #pragma unroll
        for (int cc = 0; cc < 8; cc++) w[cc] = w1s[(tc + 32 * cc) * 129 + r];
        #pragma unroll
        for (int q = 0; q < 4; q++) e[q] = Es[(tr * 4 + q) * 128 + r];
        #pragma unroll
        for (int cc = 0; cc < 8; cc++)
            #pragma unroll
            for (int q = 0; q < 4; q++) acc[cc][q] += w[cc] * e[q];
    }

    #pragma unroll
    for (int cc = 0; cc < 8; cc++) {
        int c = tc + 32 * cc;
        float bb = b1[c];
        #pragma unroll
        for (int q = 0; q < 4; q++) {
            int rr = tr * 4 + q;
            if (rr < rows) {
                float v = acc[cc][q] + bb;
                g_P[(gbase + rr) * CH + c] = v > 0.f ? v : 0.f;
            }
        }
    }
}

// ---------------------------------------------------------------------------
// Kernel A2:  Q[f, d] = sum_c P[f, c] * w2[d, c, m(f)]
// w2 chunk staged transposed in smem (stride 257).
// ---------------------------------------------------------------------------
#define SMEM_A2 ((32 * 257 + 32 * 256) * 4)
__global__ __launch_bounds__(256) void kA2(const float* __restrict__ w2)
{
    extern __shared__ float sm[];
    float* w2s = sm;             // [32 c][257] holding d values
    float* Ps  = sm + 32 * 257;  // [32 rr][256 c]

    int table, gbase, lbase, rows;
    block_map(blockIdx.x, table, gbase, lbase, rows);
    int m = table;

    int tid = threadIdx.x;
    for (int idx = tid; idx < 32 * 256; idx += 256) {
        int rr = idx >> 8, c = idx & 255;
        Ps[idx] = (rr < rows) ? g_P[(gbase + rr) * CH + c] : 0.f;
    }

    int td = tid & 31, tr = tid >> 5;
    float acc[8][4];
    #pragma unroll
    for (int i = 0; i < 8; i++)
        #pragma unroll
        for (int q = 0; q < 4; q++) acc[i][q] = 0.f;

    for (int c0 = 0; c0 < 256; c0 += 32) {
        __syncthreads();
        for (int i = 0; i < 32; i++) {
            int lin = tid + i * 256;
            int d = lin >> 5, cl = lin & 31;
            w2s[cl * 257 + d] = w2[d * 768 + (c0 + cl) * 3 + m];
        }
        __syncthreads();
        #pragma unroll 4
        for (int c = 0; c < 32; c++) {
            float w[8], p[4];
            #pragma unroll
            for (int dd = 0; dd < 8; dd++) w[dd] = w2s[c * 257 + td + 32 * dd];
            #pragma unroll
            for (int q = 0; q < 4; q++) p[q] = Ps[(tr * 4 + q) * 256 + c0 + c];
            #pragma unroll
            for (int dd = 0; dd < 8; dd++)
                #pragma unroll
                for (int q = 0; q < 4; q++) acc[dd][q] += w[dd] * p[q];
        }
    }

    #pragma unroll
    for (int dd = 0; dd < 8; dd++) {
        int d = td + 32 * dd;
        #pragma unroll
        for (int q = 0; q < 4; q++) {
            int rr = tr * 4 + q;
            if (rr < rows) g_Q[(gbase + rr) * CH + d] = acc[dd][q];
        }
    }
}

// ---------------------------------------------------------------------------
// Kernel B: per-sample path.
//   h2  = relu(Q0[i0] + Q1[i1] + Q2[i2] + b2)        (gather, L2-resident Q)
//   h3  = relu(wfc1 @ h2 + bfc1)                     (256x256 GEMM, fp32)
//   out = relu(dot(wfc2, h3) + bfc2)                 (fused epilogue, shfl-reduce)
// Block: 256 threads, 64 samples. Thread tile 8(j) x 8(s).
// ---------------------------------------------------------------------------
#define SMEM_B ((64 * 256 + 32 * 257) * 4 + 3 * 64 * 4)
__global__ __launch_bounds__(256, 2) void kB(
    const void* __restrict__ indices,
    const float* __restrict__ b2,
    const float* __restrict__ wfc1, const float* __restrict__ bfc1,
    const float* __restrict__ wfc2, const float* __restrict__ bfc2,
    float* __restrict__ out, int B)
{
    extern __shared__ float sm[];
    float* hs  = sm;              // [64 s][256 c]
    float* wsT = sm + 64 * 256;   // [32 k][257] holding j values
    int* i0s = (int*)(wsT + 32 * 257);
    int* i1s = i0s + 64;
    int* i2s = i1s + 64;

    int b0 = blockIdx.x * 64;
    int tid = threadIdx.x;
    int nS = min(64, B - b0);

    if (tid < 64) {
        int s = tid;
        int i0 = 0, i1 = 0, i2 = 0;
        if (s < nS) {
            long long bb = (long long)(b0 + s) * 3;
            if (g_idx64) {
                const long long* ip = (const long long*)indices;
                i0 = (int)ip[bb]; i1 = (int)ip[bb + 1]; i2 = (int)ip[bb + 2];
            } else {
                const int* ip = (const int*)indices;
                i0 = ip[bb]; i1 = ip[bb + 1]; i2 = ip[bb + 2];
            }
        }
        i0s[s] = i0; i1s[s] = i1; i2s[s] = i2;
    }
    __syncthreads();

    // Gather + bias + relu into hs. Each warp: 8 samples, lanes sweep channels.
    {
        int warp = tid >> 5, lane = tid & 31;
        const float4* Q0 = (const float4*)g_Q;
        const float4* Q1 = (const float4*)(g_Q + F0 * CH);
        const float4* Q2 = (const float4*)(g_Q + (F0 + F1) * CH);
        const float4* b2v = (const float4*)b2;
        float4* hs4 = (float4*)hs;
        #pragma unroll
        for (int si = 0; si < 8; si++) {
            int s = warp * 8 + si;
            int r0 = i0s[s] * 64, r1 = i1s[s] * 64, r2 = i2s[s] * 64;
            #pragma unroll
            for (int h = 0; h < 2; h++) {
                int v = lane + 32 * h;
                float4 a = Q0[r0 + v];
                float4 b = Q1[r1 + v];
                float4 c = Q2[r2 + v];
                float4 d = b2v[v];
                float4 o;
                o.x = fmaxf(a.x + b.x + c.x + d.x, 0.f);
                o.y = fmaxf(a.y + b.y + c.y + d.y, 0.f);
                o.z = fmaxf(a.z + b.z + c.z + d.z, 0.f);
                o.w = fmaxf(a.w + b.w + c.w + d.w, 0.f);
                hs4[s * 64 + v] = o;
            }
        }
    }

    // GEMM: h3[j][s] over K=256 in chunks of 32.
    int tj = tid & 31, ts = tid >> 5;
    float acc[8][8];
    #pragma unroll
    for (int jj = 0; jj < 8; jj++)
        #pragma unroll
        for (int ss = 0; ss < 8; ss++) acc[jj][ss] = 0.f;

    for (int c0 = 0; c0 < 256; c0 += 32) {
        __syncthreads();
        #pragma unroll
        for (int i = 0; i < 32; i++) {
            int lin = tid + i * 256;
            int j = lin >> 5, k = lin & 31;
            wsT[k * 257 + j] = wfc1[j * 256 + c0 + k];
        }
        __syncthreads();
        #pragma unroll 2
        for (int k = 0; k < 32; k++) {
            float w[8], h[8];
            #pragma unroll
            for (int jj = 0; jj < 8; jj++) w[jj] = wsT[k * 257 + tj + 32 * jj];
            #pragma unroll
            for (int ss = 0; ss < 8; ss++) h[ss] = hs[(ts * 8 + ss) * 256 + c0 + k];
            #pragma unroll
            for (int jj = 0; jj < 8; jj++)
                #pragma unroll
                for (int ss = 0; ss < 8; ss++) acc[jj][ss] += w[jj] * h[ss];
        }
    }

    // Epilogue: bias + relu (fc1), fc2 dot with warp reduction, relu, store.
    float bf[8], wf[8];
    #pragma unroll
    for (int jj = 0; jj < 8; jj++) {
        bf[jj] = bfc1[tj + 32 * jj];
        wf[jj] = wfc2[tj + 32 * jj];
    }
    float part[8];
    #pragma unroll
    for (int ss = 0; ss < 8; ss++) {
        float p = 0.f;
        #pragma unroll
        for (int jj = 0; jj < 8; jj++) {
            float h3 = fmaxf(acc[jj][ss] + bf[jj], 0.f);
            p += h3 * wf[jj];
        }
        part[ss] = p;
    }
    #pragma unroll
    for (int ss = 0; ss < 8; ss++) {
        #pragma unroll
        for (int off = 16; off > 0; off >>= 1)
            part[ss] += __shfl_xor_sync(0xffffffffu, part[ss], off);
    }
    if (tj == 0) {
        float bout = bfc2[0];
        #pragma unroll
        for (int ss = 0; ss < 8; ss++) {
            int s = ts * 8 + ss;
            if (s < nS) out[b0 + s] = fmaxf(part[ss] + bout, 0.f);
        }
    }
}

// ---------------------------------------------------------------------------
extern "C" void kernel_launch(void* const* d_in, const int* in_sizes, int n_in,
                              void* d_out, int out_size)
{
    const void*  indices = d_in[0];
    const float* emb0 = (const float*)d_in[1];
    const float* emb1 = (const float*)d_in[2];
    const float* emb2 = (const float*)d_in[3];
    const float* w1   = (const float*)d_in[4];
    const float* b1   = (const float*)d_in[5];
    const float* w2   = (const float*)d_in[6];
    const float* b2   = (const float*)d_in[7];
    const float* wfc1 = (const float*)d_in[8];
    const float* bfc1 = (const float*)d_in[9];
    const float* wfc2 = (const float*)d_in[10];
    const float* bfc2 = (const float*)d_in[11];
    float* out = (float*)d_out;

    int B = in_sizes[0] / 3;

    cudaFuncSetAttribute(kA1, cudaFuncAttributeMaxDynamicSharedMemorySize, SMEM_A1);
    cudaFuncSetAttribute(kA2, cudaFuncAttributeMaxDynamicSharedMemorySize, SMEM_A2);
    cudaFuncSetAttribute(kB,  cudaFuncAttributeMaxDynamicSharedMemorySize, SMEM_B);

    detect_idx_kernel<<<1, 32>>>((const unsigned int*)indices);
    kA1<<<196, 256, SMEM_A1>>>(emb0, emb1, emb2, w1, b1);
    kA2<<<196, 256, SMEM_A2>>>(w2);
    int nb = (B + 63) / 64;
    kB<<<nb, 256, SMEM_B>>>(indices, b2, wfc1, bfc1, wfc2, bfc2, out, B);
}

// round 5
// speedup vs baseline: 2.5168x; 2.5168x over previous
#include <cuda_runtime.h>
#include <cstdint>

#define F0 339
#define F1 5825
#define F2 64
#define NROWS 6228
#define RK 128
#define CH 256

__device__ float g_P[NROWS * CH];
__device__ float g_Q[NROWS * CH];
__device__ int g_idx64;

// ============================ helpers ============================
__device__ __forceinline__ uint32_t smem_u32(const void* p) {
    uint32_t a;
    asm("{ .reg .u64 t; cvta.to.shared.u64 t, %1; cvt.u32.u64 %0, t; }" : "=r"(a) : "l"(p));
    return a;
}
__device__ __forceinline__ uint32_t f2tf32(float x) {
    uint32_t u;
    asm("cvt.rna.tf32.f32 %0, %1;" : "=r"(u) : "f"(x));
    return u;
}
#define MMA_TF32(d, a, b) \
    asm volatile("mma.sync.aligned.m16n8k8.row.col.f32.tf32.tf32.f32 " \
        "{%0,%1,%2,%3}, {%4,%5,%6,%7}, {%8,%9}, {%0,%1,%2,%3};" \
        : "+f"((d)[0]), "+f"((d)[1]), "+f"((d)[2]), "+f"((d)[3]) \
        : "r"((a)[0]), "r"((a)[1]), "r"((a)[2]), "r"((a)[3]), \
          "r"((b)[0]), "r"((b)[1]))
#define CP_ASYNC16(dst, src) \
    asm volatile("cp.async.cg.shared.global [%0], [%1], 16;" :: "r"(dst), "l"(src))
#define CP_COMMIT() asm volatile("cp.async.commit_group;" ::: "memory")
#define CP_WAIT(n)  asm volatile("cp.async.wait_group %0;" :: "n"(n) : "memory")

// ============================ dtype detect ============================
__global__ void detect_idx_kernel(const unsigned int* __restrict__ w) {
    if (threadIdx.x == 0) {
        int allz = 1;
        #pragma unroll 1
        for (int i = 1; i < 256; i += 2) allz &= (w[i] == 0u);
        g_idx64 = allz;
    }
}

// ============================ precompute (proven R1 versions) ============================
__device__ __forceinline__ void block_map(int b, int& table, int& gbase, int& lbase, int& rows) {
    if (b < 11)       { table = 0; int f = b * 32;         lbase = f; gbase = f;           rows = min(32, F0 - f); }
    else if (b < 194) { table = 1; int f = (b - 11) * 32;  lbase = f; gbase = F0 + f;      rows = min(32, F1 - f); }
    else              { table = 2; int f = (b - 194) * 32; lbase = f; gbase = F0 + F1 + f; rows = min(32, F2 - f); }
}

#define SMEM_A1 ((256 * 129 + 32 * 128) * 4)
__global__ __launch_bounds__(256) void kA1(
    const float* __restrict__ emb0, const float* __restrict__ emb1,
    const float* __restrict__ emb2,
    const float* __restrict__ w1, const float* __restrict__ b1)
{
    extern __shared__ float sm[];
    float* w1s = sm;
    float* Es  = sm + 256 * 129;
    int table, gbase, lbase, rows;
    block_map(blockIdx.x, table, gbase, lbase, rows);
    const float* E = (table == 0) ? emb0 : ((table == 1) ? emb1 : emb2);
    int tid = threadIdx.x;
    for (int idx = tid; idx < 256 * 128; idx += 256) {
        int c = idx >> 7, r = idx & 127;
        w1s[c * 129 + r] = w1[idx];
    }
    for (int idx = tid; idx < 32 * 128; idx += 256) {
        int rr = idx >> 7, r = idx & 127;
        Es[idx] = (rr < rows) ? E[(long long)(lbase + rr) * RK + r] : 0.f;
    }
    __syncthreads();
    int tc = tid & 31, tr = tid >> 5;
    float acc[8][4];
    #pragma unroll
    for (int i = 0; i < 8; i++)
        #pragma unroll
        for (int q = 0; q < 4; q++) acc[i][q] = 0.f;
    #pragma unroll 4
    for (int r = 0; r < 128; r++) {
        float w[8], e[4];
        #pragma unroll
        for (int cc = 0; cc < 8; cc++) w[cc] = w1s[(tc + 32 * cc) * 129 + r];
        #pragma unroll
        for (int q = 0; q < 4; q++) e[q] = Es[(tr * 4 + q) * 128 + r];
        #pragma unroll
        for (int cc = 0; cc < 8; cc++)
            #pragma unroll
            for (int q = 0; q < 4; q++) acc[cc][q] += w[cc] * e[q];
    }
    #pragma unroll
    for (int cc = 0; cc < 8; cc++) {
        int c = tc + 32 * cc;
        float bb = b1[c];
        #pragma unroll
        for (int q = 0; q < 4; q++) {
            int rr = tr * 4 + q;
            if (rr < rows) {
                float v = acc[cc][q] + bb;
                g_P[(gbase + rr) * CH + c] = v > 0.f ? v : 0.f;
            }
        }
    }
}

#define SMEM_A2 ((32 * 257 + 32 * 256) * 4)
__global__ __launch_bounds__(256) void kA2(const float* __restrict__ w2)
{
    extern __shared__ float sm[];
    float* w2s = sm;
    float* Ps  = sm + 32 * 257;
    int table, gbase, lbase, rows;
    block_map(blockIdx.x, table, gbase, lbase, rows);
    int m = table;
    int tid = threadIdx.x;
    for (int idx = tid; idx < 32 * 256; idx += 256) {
        int rr = idx >> 8, c = idx & 255;
        Ps[idx] = (rr < rows) ? g_P[(gbase + rr) * CH + c] : 0.f;
    }
    int td = tid & 31, tr = tid >> 5;
    float acc[8][4];
    #pragma unroll
    for (int i = 0; i < 8; i++)
        #pragma unroll
        for (int q = 0; q < 4; q++) acc[i][q] = 0.f;
    for (int c0 = 0; c0 < 256; c0 += 32) {
        __syncthreads();
        for (int i = 0; i < 32; i++) {
            int lin = tid + i * 256;
            int d = lin >> 5, cl = lin & 31;
            w2s[cl * 257 + d] = w2[d * 768 + (c0 + cl) * 3 + m];
        }
        __syncthreads();
        #pragma unroll 4
        for (int c = 0; c < 32; c++) {
            float w[8], p[4];
            #pragma unroll
            for (int dd = 0; dd < 8; dd++) w[dd] = w2s[c * 257 + td + 32 * dd];
            #pragma unroll
            for (int q = 0; q < 4; q++) p[q] = Ps[(tr * 4 + q) * 256 + c0 + c];
            #pragma unroll
            for (int dd = 0; dd < 8; dd++)
                #pragma unroll
                for (int q = 0; q < 4; q++) acc[dd][q] += w[dd] * p[q];
        }
    }
    #pragma unroll
    for (int dd = 0; dd < 8; dd++) {
        int d = td + 32 * dd;
        #pragma unroll
        for (int q = 0; q < 4; q++) {
            int rr = tr * 4 + q;
            if (rr < rows) g_Q[(gbase + rr) * CH + d] = acc[dd][q];
        }
    }
}

// ============================ kernel B: mma.sync tf32, 512 threads ============================
// CTA = 128 samples. 16 warps = 4(M) x 4(N); warp tile 32(M) x 64(N).
// Full N coverage: wn in 0..3 covers j = 0..255.
#define SA 260
#define SB 36
#define NCH 8
#define BUF_F 9216                  // 256*36
#define OFF_B   33800               // As = 128*260
#define OFF_IDX 52232
#define OFF_BF1 52616
#define OFF_WF2 52872
#define OFF_PS  53128               // 512 floats
#define SMEM_KB ((53128 + 512) * 4) // 214,560 B

__global__ __launch_bounds__(512) void kB_mma(
    const void* __restrict__ indices,
    const float* __restrict__ b2,
    const float* __restrict__ wfc1, const float* __restrict__ bfc1,
    const float* __restrict__ wfc2, const float* __restrict__ bfc2,
    float* __restrict__ out, int B)
{
    extern __shared__ float sm[];
    float* As   = sm;
    float* Bs   = sm + OFF_B;
    int*   idxs = (int*)(sm + OFF_IDX);
    float* bf1s = sm + OFF_BF1;
    float* wf2s = sm + OFF_WF2;
    float* psum = sm + OFF_PS;
    const uint32_t sb = smem_u32(sm);

    int tid = threadIdx.x;
    int w = tid >> 5, lane = tid & 31;
    int g = lane >> 2, tig = lane & 3;
    int wm = w & 3, wn = w >> 2;        // wn in 0..3
    int b0 = blockIdx.x * 128;

    // ---- indices + small vectors ----
    if (tid < 128) {
        long long sg = b0 + tid;
        if (sg > (long long)B - 1) sg = B - 1;
        long long bb = sg * 3;
        int i0, i1, i2;
        if (g_idx64) {
            const long long* ip = (const long long*)indices;
            i0 = (int)ip[bb]; i1 = (int)ip[bb + 1]; i2 = (int)ip[bb + 2];
        } else {
            const int* ip = (const int*)indices;
            i0 = ip[bb]; i1 = ip[bb + 1]; i2 = ip[bb + 2];
        }
        idxs[tid * 3] = i0; idxs[tid * 3 + 1] = i1; idxs[tid * 3 + 2] = i2;
    }
    if (tid < 256) bf1s[tid] = bfc1[tid];
    else if (tid < 512) wf2s[tid - 256] = wfc2[tid - 256];

    // ---- prefetch B chunk 0 ----
    {
        const float* src0 = wfc1;
        #pragma unroll
        for (int i = 0; i < 4; ++i) {
            int lin = tid + i * 512;
            int n = lin >> 3, f4 = lin & 7;
            uint32_t dst = sb + (uint32_t)(OFF_B + n * SB + f4 * 4) * 4u;
            CP_ASYNC16(dst, src0 + n * 256 + f4 * 4);
        }
        CP_COMMIT();
    }
    __syncthreads();

    // ---- gather h2 into A (tf32 bits), stride 260; 8 samples per warp ----
    {
        const float4* Q0 = (const float4*)g_Q;
        const float4* Q1 = (const float4*)(g_Q + F0 * CH);
        const float4* Q2 = (const float4*)(g_Q + (F0 + F1) * CH);
        const float4* b2v = (const float4*)b2;
        float4 d0 = b2v[lane];
        float4 d1 = b2v[lane + 32];
        #pragma unroll 4
        for (int it = 0; it < 8; ++it) {
            int s = w * 8 + it;
            int i0 = idxs[s * 3], i1 = idxs[s * 3 + 1], i2 = idxs[s * 3 + 2];
            #pragma unroll
            for (int h = 0; h < 2; ++h) {
                int f4 = lane + 32 * h;
                float4 a = Q0[i0 * 64 + f4];
                float4 bq = Q1[i1 * 64 + f4];
                float4 cq = Q2[i2 * 64 + f4];
                float4 d = h ? d1 : d0;
                uint4 t;
                t.x = f2tf32(fmaxf(a.x + bq.x + cq.x + d.x, 0.f));
                t.y = f2tf32(fmaxf(a.y + bq.y + cq.y + d.y, 0.f));
                t.z = f2tf32(fmaxf(a.z + bq.z + cq.z + d.z, 0.f));
                t.w = f2tf32(fmaxf(a.w + bq.w + cq.w + d.w, 0.f));
                *(uint4*)(As + s * SA + f4 * 4) = t;
            }
        }
    }

    // ---- GEMM over 8 K-chunks, double-buffered B ----
    float acc[2][8][4];
    #pragma unroll
    for (int mt = 0; mt < 2; mt++)
        #pragma unroll
        for (int nt = 0; nt < 8; nt++)
            #pragma unroll
            for (int q = 0; q < 4; q++) acc[mt][nt][q] = 0.f;

    for (int c = 0; c < NCH; ++c) {
        if (c + 1 < NCH) {
            int buf = (c + 1) & 1;
            const float* src = wfc1 + (c + 1) * 32;
            #pragma unroll
            for (int i = 0; i < 4; ++i) {
                int lin = tid + i * 512;
                int n = lin >> 3, f4 = lin & 7;
                uint32_t dst = sb + (uint32_t)(OFF_B + buf * BUF_F + n * SB + f4 * 4) * 4u;
                CP_ASYNC16(dst, src + n * 256 + f4 * 4);
            }
            CP_COMMIT();
            CP_WAIT(1);
        } else {
            CP_WAIT(0);
        }
        __syncthreads();

        const float* Bb = Bs + (c & 1) * BUF_F;
        #pragma unroll
        for (int kk = 0; kk < 4; ++kk) {
            int kg = c * 32 + kk * 8;
            int kl = kk * 8;
            uint32_t a[2][4], b[8][2];
            #pragma unroll
            for (int mt = 0; mt < 2; ++mt) {
                const float* ap = As + (wm * 32 + mt * 16 + g) * SA + kg + tig;
                a[mt][0] = __float_as_uint(ap[0]);
                a[mt][1] = __float_as_uint(ap[8 * SA]);
                a[mt][2] = __float_as_uint(ap[4]);
                a[mt][3] = __float_as_uint(ap[8 * SA + 4]);
            }
            #pragma unroll
            for (int nt = 0; nt < 8; ++nt) {
                const float* bp = Bb + (wn * 64 + nt * 8 + g) * SB + kl + tig;
                b[nt][0] = __float_as_uint(bp[0]);
                b[nt][1] = __float_as_uint(bp[4]);
            }
            #pragma unroll
            for (int mt = 0; mt < 2; ++mt)
                #pragma unroll
                for (int nt = 0; nt < 8; ++nt)
                    MMA_TF32(acc[mt][nt], a[mt], b[nt]);
        }
        __syncthreads();
    }

    // ---- epilogue: fc1 bias+relu, fc2 dot, quad reduce, combine 4 N-quadrants ----
    #pragma unroll
    for (int mt = 0; mt < 2; ++mt) {
        float p0 = 0.f, p1 = 0.f;
        #pragma unroll
        for (int nt = 0; nt < 8; ++nt) {
            int j = wn * 64 + nt * 8 + tig * 2;
            float bj0 = bf1s[j], bj1 = bf1s[j + 1];
            float wj0 = wf2s[j], wj1 = wf2s[j + 1];
            float h;
            h = acc[mt][nt][0] + bj0; h = h > 0.f ? h : 0.f; p0 += h * wj0;
            h = acc[mt][nt][1] + bj1; h = h > 0.f ? h : 0.f; p0 += h * wj1;
            h = acc[mt][nt][2] + bj0; h = h > 0.f ? h : 0.f; p1 += h * wj0;
            h = acc[mt][nt][3] + bj1; h = h > 0.f ? h : 0.f; p1 += h * wj1;
        }
        p0 += __shfl_xor_sync(0xffffffffu, p0, 1);
        p0 += __shfl_xor_sync(0xffffffffu, p0, 2);
        p1 += __shfl_xor_sync(0xffffffffu, p1, 1);
        p1 += __shfl_xor_sync(0xffffffffu, p1, 2);
        if (tig == 0) {
            int r = wm * 32 + mt * 16 + g;
            psum[wn * 128 + r] = p0;
            psum[wn * 128 + r + 8] = p1;
        }
    }
    __syncthreads();
    if (tid < 128) {
        int sg = b0 + tid;
        if (sg < B)
            out[sg] = fmaxf(psum[tid] + psum[128 + tid] + psum[256 + tid] + psum[384 + tid] + bfc2[0], 0.f);
    }
}

// ============================ launch ============================
extern "C" void kernel_launch(void* const* d_in, const int* in_sizes, int n_in,
                              void* d_out, int out_size)
{
    const void*  indices = d_in[0];
    const float* emb0 = (const float*)d_in[1];
    const float* emb1 = (const float*)d_in[2];
    const float* emb2 = (const float*)d_in[3];
    const float* w1   = (const float*)d_in[4];
    const float* b1   = (const float*)d_in[5];
    const float* w2   = (const float*)d_in[6];
    const float* b2   = (const float*)d_in[7];
    const float* wfc1 = (const float*)d_in[8];
    const float* bfc1 = (const float*)d_in[9];
    const float* wfc2 = (const float*)d_in[10];
    const float* bfc2 = (const float*)d_in[11];
    float* out = (float*)d_out;

    int B = in_sizes[0] / 3;

    cudaFuncSetAttribute(kA1,    cudaFuncAttributeMaxDynamicSharedMemorySize, SMEM_A1);
    cudaFuncSetAttribute(kA2,    cudaFuncAttributeMaxDynamicSharedMemorySize, SMEM_A2);
    cudaFuncSetAttribute(kB_mma, cudaFuncAttributeMaxDynamicSharedMemorySize, SMEM_KB);

    detect_idx_kernel<<<1, 32>>>((const unsigned int*)indices);
    kA1<<<196, 256, SMEM_A1>>>(emb0, emb1, emb2, w1, b1);
    kA2<<<196, 256, SMEM_A2>>>(w2);
    int nb = (B + 127) / 128;
    kB_mma<<<nb, 512, SMEM_KB>>>(indices, b2, wfc1, bfc1, wfc2, bfc2, out, B);
}